// round 2
// baseline (speedup 1.0000x reference)
#include <cuda_runtime.h>
#include <cstdint>

#define KDIM 7168
#define ODIM 16384
#define MDIM 32
#define OTILE 128
#define KTILE 128
#define NKT (KDIM / KTILE)     /* 56 */
#define NTHREADS 256           /* 8 warps */
#define XS_STRIDE 132          /* 128 + 4 pad -> conflict-free B-fragment LDS */

// round-to-nearest fp32 -> tf32 (result in low 19 bits semantics, stored as b32)
__device__ __forceinline__ uint32_t tf32r(float v) {
    uint32_t u;
    asm("cvt.rna.tf32.f32 %0, %1;" : "=r"(u) : "f"(v));
    return u;
}

__global__ __launch_bounds__(NTHREADS, 1)
void linear_tf32_mma(const float* __restrict__ X, const float* __restrict__ W,
                     const float* __restrict__ S, float* __restrict__ out)
{
    __shared__ uint32_t xs[MDIM * XS_STRIDE];   // x tile, scaled + tf32-rounded

    const int tid  = threadIdx.x;
    const int lane = tid & 31;
    const int w    = tid >> 5;          // warp id: owns o rows [w*16, w*16+16)
    const int bx   = blockIdx.x;
    const int o_base = bx * OTILE;

    const int g = lane >> 2;            // groupID (0..7)
    const int c = lane & 3;             // threadID_in_group (0..3)

    // W fragment base pointer: A row = o_base + w*16 + g, col offset = c
    const float* Wp = W + (size_t)(o_base + w * 16 + g) * KDIM + c;

    // accumulators: 4 m-tiles (n=8 each) x 4 regs
    float acc[4][4];
    #pragma unroll
    for (int i = 0; i < 4; i++)
        #pragma unroll
        for (int j = 0; j < 4; j++) acc[i][j] = 0.0f;

    // register prefetch of x tile kt=0 (4 float4 per thread = 32x128 tile)
    float4 xr[4];
    #pragma unroll
    for (int i = 0; i < 4; i++) {
        int idx = i * NTHREADS + tid;
        int m = idx >> 5, c4 = idx & 31;
        xr[i] = *reinterpret_cast<const float4*>(X + (size_t)m * KDIM + (size_t)c4 * 4);
    }

    #pragma unroll 1
    for (int kt = 0; kt < NKT; kt++) {
        const float s = S[(size_t)bx * NKT + kt];   // scale for (o-block bx, k-block kt)

        // store x tile into smem: scaled by s, rounded to tf32
        #pragma unroll
        for (int i = 0; i < 4; i++) {
            int idx = i * NTHREADS + tid;
            int m = idx >> 5, c4 = idx & 31;
            uint32_t* p = &xs[m * XS_STRIDE + c4 * 4];
            p[0] = tf32r(xr[i].x * s);
            p[1] = tf32r(xr[i].y * s);
            p[2] = tf32r(xr[i].z * s);
            p[3] = tf32r(xr[i].w * s);
        }
        __syncthreads();

        // prefetch next x tile (latency hidden under the MMA loop)
        if (kt + 1 < NKT) {
            #pragma unroll
            for (int i = 0; i < 4; i++) {
                int idx = i * NTHREADS + tid;
                int m = idx >> 5, c4 = idx & 31;
                xr[i] = *reinterpret_cast<const float4*>(
                    X + (size_t)m * KDIM + (size_t)(kt + 1) * KTILE + (size_t)c4 * 4);
            }
        }

        const float* Wk = Wp + (size_t)kt * KTILE;

        // 16 k-steps of 8 over this K-tile; W fragments straight from GMEM
        #pragma unroll
        for (int ks = 0; ks < 16; ks++) {
            const int k0 = ks * 8;
            uint32_t a0 = tf32r(Wk[k0]);
            uint32_t a1 = tf32r(Wk[(size_t)8 * KDIM + k0]);
            uint32_t a2 = tf32r(Wk[k0 + 4]);
            uint32_t a3 = tf32r(Wk[(size_t)8 * KDIM + k0 + 4]);

            #pragma unroll
            for (int mt = 0; mt < 4; mt++) {
                uint32_t b0 = xs[(mt * 8 + g) * XS_STRIDE + k0 + c];
                uint32_t b1 = xs[(mt * 8 + g) * XS_STRIDE + k0 + 4 + c];
                asm volatile(
                    "mma.sync.aligned.m16n8k8.row.col.f32.tf32.tf32.f32 "
                    "{%0,%1,%2,%3}, {%4,%5,%6,%7}, {%8,%9}, {%0,%1,%2,%3};"
                    : "+f"(acc[mt][0]), "+f"(acc[mt][1]),
                      "+f"(acc[mt][2]), "+f"(acc[mt][3])
                    : "r"(a0), "r"(a1), "r"(a2), "r"(a3), "r"(b0), "r"(b1));
            }
        }
        __syncthreads();   // protect xs before next tile's stores
    }

    // epilogue: D fragment mapping for m16n8k8:
    //   d0: (row=g,   col=2c)   d1: (row=g,   col=2c+1)
    //   d2: (row=g+8, col=2c)   d3: (row=g+8, col=2c+1)
    // rows = o within warp tile, cols = m within m-tile. out is [M, O] row-major.
    const int o0 = o_base + w * 16 + g;
    #pragma unroll
    for (int mt = 0; mt < 4; mt++) {
        const int m0 = mt * 8 + c * 2;
        out[(size_t)m0       * ODIM + o0    ] = acc[mt][0];
        out[(size_t)(m0 + 1) * ODIM + o0    ] = acc[mt][1];
        out[(size_t)m0       * ODIM + o0 + 8] = acc[mt][2];
        out[(size_t)(m0 + 1) * ODIM + o0 + 8] = acc[mt][3];
    }
}

extern "C" void kernel_launch(void* const* d_in, const int* in_sizes, int n_in,
                              void* d_out, int out_size) {
    const float* x = (const float*)d_in[0];
    const float* w = (const float*)d_in[1];
    const float* s = (const float*)d_in[2];
    float* out = (float*)d_out;

    linear_tf32_mma<<<ODIM / OTILE, NTHREADS>>>(x, w, s, out);
}

// round 3
// speedup vs baseline: 1.3532x; 1.3532x over previous
#include <cuda_runtime.h>
#include <cstdint>

#define KDIM 7168
#define ODIM 16384
#define MDIM 32
#define OTILE 128
#define KTILE 128
#define NKT (KDIM / KTILE)     /* 56 */
#define NTHREADS 256           /* 8 warps */
#define WS_STRIDE 132          /* 128 + 4 pad floats -> conflict-free fragment LDS */
#define W_STAGE (128 * WS_STRIDE)          /* floats per W stage: 16896 */
#define NSTAGE 3
#define XS_STRIDE 132

// dynamic smem: [ W stages: 3 * 16896 floats ][ xs: 32 * 132 u32 ]
#define SMEM_FLOATS (NSTAGE * W_STAGE + MDIM * XS_STRIDE)

__device__ __forceinline__ uint32_t smem_u32(const void* p) {
    uint32_t a;
    asm("{ .reg .u64 t; cvta.to.shared.u64 t, %1; cvt.u32.u64 %0, t; }" : "=r"(a) : "l"(p));
    return a;
}

__device__ __forceinline__ uint32_t tf32r(float v) {   // fp32 -> tf32 round-to-nearest
    uint32_t u;
    asm("cvt.rna.tf32.f32 %0, %1;" : "=r"(u) : "f"(v));
    return u;
}

__device__ __forceinline__ void cp_async16(uint32_t dst_smem, const void* src) {
    asm volatile("cp.async.cg.shared.global [%0], [%1], 16;" :: "r"(dst_smem), "l"(src) : "memory");
}
#define CP_COMMIT() asm volatile("cp.async.commit_group;" ::: "memory")
#define CP_WAIT2()  asm volatile("cp.async.wait_group 2;" ::: "memory")

__global__ __launch_bounds__(NTHREADS, 1)
void linear_tf32_mma(const float* __restrict__ X, const float* __restrict__ W,
                     const float* __restrict__ S, float* __restrict__ out)
{
    extern __shared__ float smem[];
    float*    wbuf = smem;
    uint32_t* xs   = reinterpret_cast<uint32_t*>(smem + NSTAGE * W_STAGE);

    const int tid  = threadIdx.x;
    const int lane = tid & 31;
    const int w    = tid >> 5;
    const int bx   = blockIdx.x;
    const int o_base = bx * OTILE;

    const int g = lane >> 2;   // 0..7
    const int c = lane & 3;    // 0..3

    // per-thread cp.async coordinates: idx = i*256+tid -> row = idx>>5, c4 = idx&31
    const int cprow = tid >> 5;           // +8*i
    const int cpc4  = tid & 31;

    float acc[4][4];
    #pragma unroll
    for (int i = 0; i < 4; i++)
        #pragma unroll
        for (int j = 0; j < 4; j++) acc[i][j] = 0.0f;

    // ---- prologue: x tile kt=0 into registers, W stages 0..2 via cp.async ----
    float4 xr[4];
    #pragma unroll
    for (int i = 0; i < 4; i++) {
        int idx = i * NTHREADS + tid;
        int m = idx >> 5, c4 = idx & 31;
        xr[i] = *reinterpret_cast<const float4*>(X + (size_t)m * KDIM + (size_t)c4 * 4);
    }

    #pragma unroll
    for (int st = 0; st < NSTAGE; st++) {
        const uint32_t dbase = smem_u32(wbuf + st * W_STAGE);
        const float*   gsrc  = W + (size_t)o_base * KDIM + (size_t)st * KTILE;
        #pragma unroll
        for (int i = 0; i < 16; i++) {
            int row = cprow + i * 8;
            cp_async16(dbase + (uint32_t)(row * WS_STRIDE + cpc4 * 4) * 4u,
                       gsrc + (size_t)row * KDIM + (size_t)cpc4 * 4);
        }
        CP_COMMIT();
    }

    #pragma unroll 1
    for (int kt = 0; kt < NKT; kt++) {
        const float s = S[(size_t)bx * NKT + kt];

        // scaled + tf32-rounded x tile -> smem
        #pragma unroll
        for (int i = 0; i < 4; i++) {
            int idx = i * NTHREADS + tid;
            int m = idx >> 5, c4 = idx & 31;
            uint32_t* p = &xs[m * XS_STRIDE + c4 * 4];
            p[0] = tf32r(xr[i].x * s);
            p[1] = tf32r(xr[i].y * s);
            p[2] = tf32r(xr[i].z * s);
            p[3] = tf32r(xr[i].w * s);
        }

        CP_WAIT2();            // W stage kt resident
        __syncthreads();       // xs + W visible to all warps

        // prefetch next x tile (L2-resident, hidden under MMA)
        if (kt + 1 < NKT) {
            #pragma unroll
            for (int i = 0; i < 4; i++) {
                int idx = i * NTHREADS + tid;
                int m = idx >> 5, c4 = idx & 31;
                xr[i] = *reinterpret_cast<const float4*>(
                    X + (size_t)m * KDIM + (size_t)(kt + 1) * KTILE + (size_t)c4 * 4);
            }
        }

        const float* wstage = wbuf + (kt % NSTAGE) * W_STAGE;
        const int r0 = w * 16 + g;

        #pragma unroll
        for (int ks = 0; ks < 16; ks++) {
            const int k0 = ks * 8;
            uint32_t a0 = tf32r(wstage[ r0      * WS_STRIDE + k0 + c    ]);
            uint32_t a1 = tf32r(wstage[(r0 + 8) * WS_STRIDE + k0 + c    ]);
            uint32_t a2 = tf32r(wstage[ r0      * WS_STRIDE + k0 + c + 4]);
            uint32_t a3 = tf32r(wstage[(r0 + 8) * WS_STRIDE + k0 + c + 4]);

            #pragma unroll
            for (int mt = 0; mt < 4; mt++) {
                uint32_t b0 = xs[(mt * 8 + g) * XS_STRIDE + k0 + c];
                uint32_t b1 = xs[(mt * 8 + g) * XS_STRIDE + k0 + 4 + c];
                asm volatile(
                    "mma.sync.aligned.m16n8k8.row.col.f32.tf32.tf32.f32 "
                    "{%0,%1,%2,%3}, {%4,%5,%6,%7}, {%8,%9}, {%0,%1,%2,%3};"
                    : "+f"(acc[mt][0]), "+f"(acc[mt][1]),
                      "+f"(acc[mt][2]), "+f"(acc[mt][3])
                    : "r"(a0), "r"(a1), "r"(a2), "r"(a3), "r"(b0), "r"(b1));
            }
        }

        __syncthreads();       // all warps done reading wstage + xs

        // refill this stage's buffer with tile kt+NSTAGE (or commit empty group)
        if (kt + NSTAGE < NKT) {
            const uint32_t dbase = smem_u32(wbuf + (kt % NSTAGE) * W_STAGE);
            const float*   gsrc  = W + (size_t)o_base * KDIM + (size_t)(kt + NSTAGE) * KTILE;
            #pragma unroll
            for (int i = 0; i < 16; i++) {
                int row = cprow + i * 8;
                cp_async16(dbase + (uint32_t)(row * WS_STRIDE + cpc4 * 4) * 4u,
                           gsrc + (size_t)row * KDIM + (size_t)cpc4 * 4);
            }
        }
        CP_COMMIT();
    }

    // epilogue: d0:(g,2c) d1:(g,2c+1) d2:(g+8,2c) d3:(g+8,2c+1); rows=o, cols=m
    const int o0 = o_base + w * 16 + g;
    #pragma unroll
    for (int mt = 0; mt < 4; mt++) {
        const int m0 = mt * 8 + c * 2;
        out[(size_t)m0       * ODIM + o0    ] = acc[mt][0];
        out[(size_t)(m0 + 1) * ODIM + o0    ] = acc[mt][1];
        out[(size_t)m0       * ODIM + o0 + 8] = acc[mt][2];
        out[(size_t)(m0 + 1) * ODIM + o0 + 8] = acc[mt][3];
    }
}

extern "C" void kernel_launch(void* const* d_in, const int* in_sizes, int n_in,
                              void* d_out, int out_size) {
    const float* x = (const float*)d_in[0];
    const float* w = (const float*)d_in[1];
    const float* s = (const float*)d_in[2];
    float* out = (float*)d_out;

    const size_t smem_bytes = SMEM_FLOATS * sizeof(float);
    cudaFuncSetAttribute(linear_tf32_mma,
                         cudaFuncAttributeMaxDynamicSharedMemorySize, (int)smem_bytes);
    linear_tf32_mma<<<ODIM / OTILE, NTHREADS, smem_bytes>>>(x, w, s, out);
}